// round 16
// baseline (speedup 1.0000x reference)
#include <cuda_runtime.h>
#include <cuda_fp16.h>
#include <mma.h>
#include <cuda_pipeline.h>
#include <math.h>

using namespace nvcuda;

// Problem dims
#define MROWS 16384            // B*S
#define DDIM  2048             // D
#define MSZ   ((size_t)MROWS * DDIM)
#define WSZ   ((size_t)DDIM * DDIM)

// ---------------- device scratch (allocation-free rule) ------------------------
__device__ __half g_Ah[MSZ];               // activations fp16 (X, then X1)
__device__ __half g_Hh[MSZ];               // gelu output fp16
__device__ __half g_Wf[5 * WSZ];           // weights fp16 [K,N] row-major
__device__ __half g_Qh[MSZ];               // Q fp16; later reused as y2
__device__ __half g_Kh[MSZ];
__device__ __half g_Vh[MSZ];

// ---------------- fused convert: X + 5 weights to fp16 in ONE launch ------------
__global__ void __launch_bounds__(256)
split_all_kernel(const float* __restrict__ X,
                 const float* __restrict__ W0, const float* __restrict__ W1,
                 const float* __restrict__ W2, const float* __restrict__ W3,
                 const float* __restrict__ W4,
                 __half* __restrict__ Ah, __half* __restrict__ Wf)
{
    const int which = blockIdx.y;
    int i = blockIdx.x * 256 + threadIdx.x;
    const float* src;
    __half* oh;
    int n4;
    if (which == 0) {
        src = X; oh = Ah; n4 = (MROWS * DDIM) / 4;
    } else {
        const float* Ws[5] = {W0, W1, W2, W3, W4};
        src = Ws[which - 1];
        oh = Wf + (size_t)(which - 1) * WSZ;
        n4 = (DDIM * DDIM) / 4;
    }
    if (i >= n4) return;
    float4 v = ((const float4*)src)[i];
    __half2 h0 = {__float2half(v.x), __float2half(v.y)};
    __half2 h1 = {__float2half(v.z), __float2half(v.w)};
    ((__half2*)oh)[2 * i]     = h0;
    ((__half2*)oh)[2 * i + 1] = h1;
}

// ================= fp16 GEMM body (HMMA): O = A x B (+bias [+gelu]) ============
// CTA 128x128, BK=64, 3-stage cp.async, 8 warps of 64x32, 2 CTAs/SM.
constexpr int BM = 128, BN = 128, BK = 64;
constexpr int NSTG = 3;
constexpr int APAD = 8,  LDA = BK + APAD;     // 72
constexpr int BPAD = 8,  LDB = BN + BPAD;     // 136
constexpr int A_BYTES = BM * LDA * 2;         // 18432
constexpr int B_BYTES = BK * LDB * 2;         // 17408
constexpr int STG_BYTES = A_BYTES + B_BYTES;  // 35840
constexpr int GEMM_SMEM = NSTG * STG_BYTES;   // 107520 (x2 CTAs = 215040 < 228K)

template<int EPI>   // 0: bias; 1: bias + exact GELU
__device__ __forceinline__ void gemm_body(char* dsm,
          const __half* __restrict__ A,
          const __half* __restrict__ Bf,
          const float* __restrict__ bias,
          __half* __restrict__ Oh,
          int m0, int n0)
{
    constexpr int K = DDIM, N = DDIM;
    const int tid  = threadIdx.x;
    const int warp = tid >> 5, lane = tid & 31;
    const int wr = warp >> 2;          // 0..1 -> 64-row slab
    const int wc = warp & 3;           // 0..3 -> 32-col slab

    wmma::fragment<wmma::accumulator, 16, 16, 16, float> acc[4][2];
    #pragma unroll
    for (int i = 0; i < 4; i++)
        #pragma unroll
        for (int j = 0; j < 2; j++) wmma::fill_fragment(acc[i][j], 0.0f);

    auto load_stage = [&](int s, int kk) {
        __half* sA = (__half*)(dsm + s * STG_BYTES);
        __half* sB = (__half*)(dsm + s * STG_BYTES + A_BYTES);
        #pragma unroll
        for (int r = 0; r < 4; r++) {              // A: 128x64 = 1024 x 16B
            int idx = tid + r * 256;
            int row = idx >> 3, c8 = (idx & 7) * 8;
            __pipeline_memcpy_async(sA + row * LDA + c8,
                                    A + (size_t)(m0 + row) * K + kk + c8, 16);
        }
        #pragma unroll
        for (int r = 0; r < 4; r++) {              // B: 64x128 = 1024 x 16B
            int idx = tid + r * 256;
            int row = idx >> 4, c8 = (idx & 15) * 8;
            __pipeline_memcpy_async(sB + row * LDB + c8,
                                    Bf + (size_t)(kk + row) * N + n0 + c8, 16);
        }
    };

    const int nIter = K / BK;   // 32
    load_stage(0, 0);             __pipeline_commit();
    load_stage(1, BK);            __pipeline_commit();

    for (int it = 0; it < nIter; ++it) {
        int cur = it % NSTG;
        __pipeline_wait_prior(1);          // stage `it` resident
        __syncthreads();                   // prev compute done before overwrite
        if (it + 2 < nIter) load_stage((it + 2) % NSTG, (it + 2) * BK);
        __pipeline_commit();

        const __half* sA = (const __half*)(dsm + cur * STG_BYTES);
        const __half* sB = (const __half*)(dsm + cur * STG_BYTES + A_BYTES);
        #pragma unroll
        for (int k2 = 0; k2 < BK; k2 += 16) {
            wmma::fragment<wmma::matrix_a, 16, 16, 16, __half, wmma::row_major> af[4];
            wmma::fragment<wmma::matrix_b, 16, 16, 16, __half, wmma::row_major> bf[2];
            #pragma unroll
            for (int i = 0; i < 4; i++)
                wmma::load_matrix_sync(af[i], sA + (wr * 64 + i * 16) * LDA + k2, LDA);
            #pragma unroll
            for (int j = 0; j < 2; j++)
                wmma::load_matrix_sync(bf[j], sB + k2 * LDB + wc * 32 + j * 16, LDB);
            #pragma unroll
            for (int i = 0; i < 4; i++)
                #pragma unroll
                for (int j = 0; j < 2; j++)
                    wmma::mma_sync(acc[i][j], af[i], bf[j], acc[i][j]);
        }
    }
    __syncthreads();

    // epilogue: per-warp smem staging, ONE 16B store (8 halves) per thread/frag
    float* buf = (float*)dsm + warp * 272;
    #pragma unroll
    for (int i = 0; i < 4; i++) {
        #pragma unroll
        for (int j = 0; j < 2; j++) {
            wmma::store_matrix_sync(buf, acc[i][j], 16, wmma::mem_row_major);
            __syncwarp();
            const int gr = m0 + wr * 64 + i * 16;
            const int gc = n0 + wc * 32 + j * 16;
            const int r  = lane >> 1, ch = (lane & 1) * 8;
            float vv[8];
            #pragma unroll
            for (int e = 0; e < 8; e++) {
                float v = buf[r * 16 + ch + e] + bias[gc + ch + e];
                if (EPI == 1) v = v * normcdff(v);     // exact GELU
                vv[e] = v;
            }
            __half2 hs[4];
            #pragma unroll
            for (int p = 0; p < 4; p++)
                hs[p] = __floats2half2_rn(vv[2 * p], vv[2 * p + 1]);
            *reinterpret_cast<int4*>(&Oh[(size_t)(gr + r) * N + gc + ch]) =
                *reinterpret_cast<int4*>(hs);
            __syncwarp();
        }
    }
}

template<int EPI>
__global__ void __launch_bounds__(256, 2)
gemm_fp16(const __half* __restrict__ A,
          const __half* __restrict__ Bf,
          const float* __restrict__ bias,
          __half* __restrict__ Oh)
{
    extern __shared__ char dsm[];
    gemm_body<EPI>(dsm, A, Bf, bias, Oh, blockIdx.y * BM, blockIdx.x * BN);
}

// Fused Q/K/V projection: grid (48, 128); blockIdx.x>>4 selects weight/out.
__global__ void __launch_bounds__(256, 2)
gemm_qkv(const __half* __restrict__ A,
         const __half* __restrict__ Wf,
         const float* __restrict__ bq, const float* __restrict__ bk,
         const float* __restrict__ bv,
         __half* __restrict__ Qh, __half* __restrict__ Kh,
         __half* __restrict__ Vh)
{
    extern __shared__ char dsm[];
    const int which = blockIdx.x >> 4;          // 0..2
    const int n0 = (blockIdx.x & 15) * BN;
    const __half* Bf;
    const float* bias;
    __half* Oh;
    if (which == 0)      { Bf = Wf;            bias = bq; Oh = Qh; }
    else if (which == 1) { Bf = Wf + WSZ;      bias = bk; Oh = Kh; }
    else                 { Bf = Wf + 2 * WSZ;  bias = bv; Oh = Vh; }
    gemm_body<0>(dsm, A, Bf, bias, Oh, blockIdx.y * BM, n0);
}

// ---------------- per-token head-attention + residual + LN1 --------------------
// Q/K/V fp16, X fp32; output X1 as fp16 (Ah) ONLY. 256 threads per token.
__global__ void __launch_bounds__(256)
attn_ln1_kernel(const __half* __restrict__ Q, const __half* __restrict__ Kk,
                const __half* __restrict__ V, const float* __restrict__ X,
                const float* __restrict__ g1, const float* __restrict__ be1,
                __half* __restrict__ Oh)
{
    __shared__ float sq[16 * 129], sk[16 * 129], sv[16 * 129];
    __shared__ float satt[16][16];
    __shared__ float red[16];
    const int t = blockIdx.x, tid = threadIdx.x;
    const size_t base4 = (size_t)t * (DDIM / 4);
    const size_t base8 = (size_t)t * (DDIM / 8);

    // load: one int4 (8 halves) per thread per tensor
    {
        int e = tid * 8, h = e >> 7, d = e & 127, o = h * 129 + d;
        int4 qa = ((const int4*)Q)[base8 + tid];
        int4 ka = ((const int4*)Kk)[base8 + tid];
        int4 va = ((const int4*)V)[base8 + tid];
        const __half2* qh = (const __half2*)&qa;
        const __half2* kh = (const __half2*)&ka;
        const __half2* vh = (const __half2*)&va;
        #pragma unroll
        for (int p = 0; p < 4; p++) {
            float2 qf = __half22float2(qh[p]);
            float2 kf = __half22float2(kh[p]);
            float2 vf = __half22float2(vh[p]);
            sq[o + 2*p] = qf.x; sq[o + 2*p + 1] = qf.y;
            sk[o + 2*p] = kf.x; sk[o + 2*p + 1] = kf.y;
            sv[o + 2*p] = vf.x; sv[o + 2*p + 1] = vf.y;
        }
    }
    __syncthreads();

    // scores: one (h,tt) pair per thread
    {
        int h = tid >> 4, tt = tid & 15;
        const float* qp = sq + h * 129;
        const float* kp = sk + tt * 129;
        float s = 0.f;
        #pragma unroll
        for (int d = 0; d < 128; d++) s += qp[d] * kp[d];
        satt[h][tt] = s * 0.08838834764831845f;     // 1/sqrt(128)
    }
    __syncthreads();

    if (tid < 16) {
        float mx = -1e30f;
        #pragma unroll
        for (int j = 0; j < 16; j++) mx = fmaxf(mx, satt[tid][j]);
        float sum = 0.f;
        #pragma unroll
        for (int j = 0; j < 16; j++) { float e = expf(satt[tid][j] - mx); satt[tid][j] = e; sum += e; }
        float inv = 1.f / sum;
        #pragma unroll
        for (int j = 0; j < 16; j++) satt[tid][j] *= inv;
    }
    __syncthreads();

    // y + residual, 8 elems per thread (two float4 of X)
    float xp[8];
    float ls = 0.f, lq = 0.f;
    #pragma unroll
    for (int it = 0; it < 2; it++) {
        int i4 = tid * 2 + it;
        int e = i4 * 4, h = e >> 7, d = e & 127;
        float4 xv = ((const float4*)X)[base4 + i4];
        float y0 = 0.f, y1 = 0.f, y2 = 0.f, y3 = 0.f;
        #pragma unroll
        for (int tt = 0; tt < 16; tt++) {
            float p = satt[h][tt];
            const float* vp = sv + tt * 129 + d;
            y0 += p * vp[0]; y1 += p * vp[1]; y2 += p * vp[2]; y3 += p * vp[3];
        }
        float v0 = xv.x + y0, v1 = xv.y + y1, v2 = xv.z + y2, v3 = xv.w + y3;
        xp[it*4+0] = v0; xp[it*4+1] = v1; xp[it*4+2] = v2; xp[it*4+3] = v3;
        ls += v0 + v1 + v2 + v3;
        lq += v0*v0 + v1*v1 + v2*v2 + v3*v3;
    }
    #pragma unroll
    for (int off = 16; off; off >>= 1) {
        ls += __shfl_xor_sync(0xffffffffu, ls, off);
        lq += __shfl_xor_sync(0xffffffffu, lq, off);
    }
    if ((tid & 31) == 0) { red[tid >> 5] = ls; red[8 + (tid >> 5)] = lq; }
    __syncthreads();
    float S = 0.f, Qs = 0.f;
    #pragma unroll
    for (int w = 0; w < 8; w++) { S += red[w]; Qs += red[8 + w]; }
    float mean = S * (1.0f / DDIM);
    float var  = Qs * (1.0f / DDIM) - mean * mean;
    float inv  = rsqrtf(var + 1e-5f);

    // normalize + write fp16 (one int4 of 8 halves)
    __half2 hs[4];
    #pragma unroll
    for (int it = 0; it < 2; it++) {
        int i4 = tid * 2 + it;
        float4 g = ((const float4*)g1)[i4];
        float4 be = ((const float4*)be1)[i4];
        float v0 = (xp[it*4+0] - mean) * inv * g.x + be.x;
        float v1 = (xp[it*4+1] - mean) * inv * g.y + be.y;
        float v2 = (xp[it*4+2] - mean) * inv * g.z + be.z;
        float v3 = (xp[it*4+3] - mean) * inv * g.w + be.w;
        hs[it*2+0] = __floats2half2_rn(v0, v1);
        hs[it*2+1] = __floats2half2_rn(v2, v3);
    }
    *reinterpret_cast<int4*>(&Oh[(size_t)t * DDIM + tid * 8]) =
        *reinterpret_cast<int4*>(hs);
}

// ---------------- out = LN(A_half + B_half) * g + beta -------------------------
__global__ void __launch_bounds__(256)
add_ln_kernel(const __half* __restrict__ A, const __half* __restrict__ Bv,
              const float* __restrict__ g, const float* __restrict__ be,
              float* __restrict__ out)
{
    __shared__ float red[16];
    const int t = blockIdx.x, tid = threadIdx.x;
    const size_t base4 = (size_t)t * (DDIM / 4);
    const size_t base8 = (size_t)t * (DDIM / 8);

    int4 aa = ((const int4*)A)[base8 + tid];
    int4 ba = ((const int4*)Bv)[base8 + tid];
    const __half2* ah = (const __half2*)&aa;
    const __half2* bh = (const __half2*)&ba;
    float xp[8];
    float ls = 0.f, lq = 0.f;
    #pragma unroll
    for (int p = 0; p < 4; p++) {
        float2 af = __half22float2(ah[p]);
        float2 bf = __half22float2(bh[p]);
        float v0 = af.x + bf.x, v1 = af.y + bf.y;
        xp[2*p] = v0; xp[2*p+1] = v1;
        ls += v0 + v1;
        lq += v0*v0 + v1*v1;
    }
    #pragma unroll
    for (int off = 16; off; off >>= 1) {
        ls += __shfl_xor_sync(0xffffffffu, ls, off);
        lq += __shfl_xor_sync(0xffffffffu, lq, off);
    }
    if ((tid & 31) == 0) { red[tid >> 5] = ls; red[8 + (tid >> 5)] = lq; }
    __syncthreads();
    float S = 0.f, Qs = 0.f;
    #pragma unroll
    for (int w = 0; w < 8; w++) { S += red[w]; Qs += red[8 + w]; }
    float mean = S * (1.0f / DDIM);
    float var  = Qs * (1.0f / DDIM) - mean * mean;
    float inv  = rsqrtf(var + 1e-5f);
    #pragma unroll
    for (int it = 0; it < 2; it++) {
        int i4 = tid * 2 + it;
        float4 gg = ((const float4*)g)[i4];
        float4 be4 = ((const float4*)be)[i4];
        float4 v;
        v.x = (xp[it*4+0] - mean) * inv * gg.x + be4.x;
        v.y = (xp[it*4+1] - mean) * inv * gg.y + be4.y;
        v.z = (xp[it*4+2] - mean) * inv * gg.z + be4.z;
        v.w = (xp[it*4+3] - mean) * inv * gg.w + be4.w;
        ((float4*)out)[base4 + i4] = v;
    }
}

// ---------------- host orchestration -------------------------------------------
extern "C" void kernel_launch(void* const* d_in, const int* in_sizes, int n_in,
                              void* d_out, int out_size)
{
    const float* X     = (const float*)d_in[0];
    const float* Wq    = (const float*)d_in[1];
    const float* bq    = (const float*)d_in[2];
    const float* Wk    = (const float*)d_in[3];
    const float* bk    = (const float*)d_in[4];
    const float* Wv    = (const float*)d_in[5];
    const float* bv    = (const float*)d_in[6];
    const float* g1    = (const float*)d_in[7];
    const float* beta1 = (const float*)d_in[8];
    const float* W1    = (const float*)d_in[9];
    const float* b1    = (const float*)d_in[10];
    const float* W2    = (const float*)d_in[11];
    const float* b2    = (const float*)d_in[12];
    const float* g2    = (const float*)d_in[13];
    const float* beta2 = (const float*)d_in[14];
    float* out = (float*)d_out;

    __half *Ah, *Hh, *Wf, *Qh, *Kh, *Vh;
    cudaGetSymbolAddress((void**)&Ah, g_Ah);
    cudaGetSymbolAddress((void**)&Hh, g_Hh);
    cudaGetSymbolAddress((void**)&Wf, g_Wf);
    cudaGetSymbolAddress((void**)&Qh, g_Qh);
    cudaGetSymbolAddress((void**)&Kh, g_Kh);
    cudaGetSymbolAddress((void**)&Vh, g_Vh);

    cudaFuncSetAttribute(gemm_fp16<0>, cudaFuncAttributeMaxDynamicSharedMemorySize, GEMM_SMEM);
    cudaFuncSetAttribute(gemm_fp16<1>, cudaFuncAttributeMaxDynamicSharedMemorySize, GEMM_SMEM);
    cudaFuncSetAttribute(gemm_qkv,     cudaFuncAttributeMaxDynamicSharedMemorySize, GEMM_SMEM);

    // launch 0: all converts fused (X + 5 weights)
    {
        int gx = (MROWS * DDIM / 4 + 255) / 256;
        dim3 gs(gx, 6);
        split_all_kernel<<<gs, 256>>>(X, Wq, Wk, Wv, W1, W2, Ah, Wf);
    }

    // launch 1: fused Q/K/V projection (one launch, 6144 CTAs)
    {
        dim3 gq(48, MROWS / BM);
        gemm_qkv<<<gq, 256, GEMM_SMEM>>>(Ah, Wf, bq, bk, bv, Qh, Kh, Vh);
    }

    // launch 2: attn + LN1 -> X1 stored fp16 in Ah
    attn_ln1_kernel<<<MROWS, 256>>>(Qh, Kh, Vh, X, g1, beta1, Ah);

    dim3 gg(DDIM / BN, MROWS / BM);   // (16, 128)
    // launch 3: FFN1 (+GELU)
    gemm_fp16<1><<<gg, 256, GEMM_SMEM>>>(Ah, Wf + 3 * WSZ, b1, Hh);
    // launch 4: FFN2 (y2 reuses Qh)
    gemm_fp16<0><<<gg, 256, GEMM_SMEM>>>(Hh, Wf + 4 * WSZ, b2, Qh);
    // launch 5: final residual + LN2  <-- ncu -s 5 -c 1 captures THIS
    add_ln_kernel<<<MROWS, 256>>>(Ah, Qh, g2, beta2, out);
}

// round 17
// speedup vs baseline: 1.1722x; 1.1722x over previous
#include <cuda_runtime.h>
#include <cuda_fp16.h>
#include <mma.h>
#include <cuda_pipeline.h>
#include <math.h>

using namespace nvcuda;

// Problem dims
#define MROWS 16384            // B*S
#define DDIM  2048             // D
#define MSZ   ((size_t)MROWS * DDIM)
#define WSZ   ((size_t)DDIM * DDIM)

// ---------------- device scratch (allocation-free rule) ------------------------
__device__ __half g_Ah[MSZ];               // activations fp16 (X, then X1)
__device__ __half g_Hh[MSZ];               // gelu output fp16
__device__ __half g_Wf[5 * WSZ];           // weights fp16 [K,N] row-major
__device__ __half g_Qh[MSZ];               // Q fp16; later reused as y2
__device__ __half g_Kh[MSZ];
__device__ __half g_Vh[MSZ];

// ---------------- convert X to fp16 --------------------------------------------
__global__ void __launch_bounds__(256)
split_x_kernel(const float* __restrict__ X, __half* __restrict__ Ah)
{
    int i = blockIdx.x * 256 + threadIdx.x;          // n4 = MSZ/4, exact grid
    float4 v = ((const float4*)X)[i];
    __half2 h0 = {__float2half(v.x), __float2half(v.y)};
    __half2 h1 = {__float2half(v.z), __float2half(v.w)};
    ((__half2*)Ah)[2 * i]     = h0;
    ((__half2*)Ah)[2 * i + 1] = h1;
}

// ---------------- convert 5 weights to fp16 ------------------------------------
__global__ void __launch_bounds__(256)
split_w_kernel(const float* __restrict__ W0, const float* __restrict__ W1,
               const float* __restrict__ W2, const float* __restrict__ W3,
               const float* __restrict__ W4, __half* __restrict__ Wf)
{
    const float* Ws[5] = {W0, W1, W2, W3, W4};
    const int which = blockIdx.y;
    const float* src = Ws[which];
    __half* oh = Wf + (size_t)which * WSZ;
    int i = blockIdx.x * 256 + threadIdx.x;          // n4 = WSZ/4, exact grid
    float4 v = ((const float4*)src)[i];
    __half2 h0 = {__float2half(v.x), __float2half(v.y)};
    __half2 h1 = {__float2half(v.z), __float2half(v.w)};
    ((__half2*)oh)[2 * i]     = h0;
    ((__half2*)oh)[2 * i + 1] = h1;
}

// ================= fp16 GEMM (HMMA): O = A x B (+bias [+gelu]), fp16 out =======
// CTA 128x128, BK=64, 3-stage cp.async, 8 warps of 64x32, 2 CTAs/SM.
constexpr int BM = 128, BN = 128, BK = 64;
constexpr int NSTG = 3;
constexpr int APAD = 8,  LDA = BK + APAD;     // 72
constexpr int BPAD = 8,  LDB = BN + BPAD;     // 136
constexpr int A_BYTES = BM * LDA * 2;         // 18432
constexpr int B_BYTES = BK * LDB * 2;         // 17408
constexpr int STG_BYTES = A_BYTES + B_BYTES;  // 35840
constexpr int GEMM_SMEM = NSTG * STG_BYTES;   // 107520 (x2 CTAs = 215040 < 228K)

template<int EPI>   // 0: bias; 1: bias + exact GELU
__global__ void __launch_bounds__(256, 2)
gemm_fp16(const __half* __restrict__ A,
          const __half* __restrict__ Bf,
          const float* __restrict__ bias,
          __half* __restrict__ Oh)
{
    constexpr int K = DDIM, N = DDIM;
    extern __shared__ char dsm[];

    const int tid  = threadIdx.x;
    const int warp = tid >> 5, lane = tid & 31;
    const int wr = warp >> 2;          // 0..1 -> 64-row slab
    const int wc = warp & 3;           // 0..3 -> 32-col slab
    const int m0 = blockIdx.y * BM, n0 = blockIdx.x * BN;

    wmma::fragment<wmma::accumulator, 16, 16, 16, float> acc[4][2];
    #pragma unroll
    for (int i = 0; i < 4; i++)
        #pragma unroll
        for (int j = 0; j < 2; j++) wmma::fill_fragment(acc[i][j], 0.0f);

    auto load_stage = [&](int s, int kk) {
        __half* sA = (__half*)(dsm + s * STG_BYTES);
        __half* sB = (__half*)(dsm + s * STG_BYTES + A_BYTES);
        #pragma unroll
        for (int r = 0; r < 4; r++) {              // A: 128x64 = 1024 x 16B
            int idx = tid + r * 256;
            int row = idx >> 3, c8 = (idx & 7) * 8;
            __pipeline_memcpy_async(sA + row * LDA + c8,
                                    A + (size_t)(m0 + row) * K + kk + c8, 16);
        }
        #pragma unroll
        for (int r = 0; r < 4; r++) {              // B: 64x128 = 1024 x 16B
            int idx = tid + r * 256;
            int row = idx >> 4, c8 = (idx & 15) * 8;
            __pipeline_memcpy_async(sB + row * LDB + c8,
                                    Bf + (size_t)(kk + row) * N + n0 + c8, 16);
        }
    };

    const int nIter = K / BK;   // 32
    load_stage(0, 0);             __pipeline_commit();
    load_stage(1, BK);            __pipeline_commit();

    for (int it = 0; it < nIter; ++it) {
        int cur = it % NSTG;
        __pipeline_wait_prior(1);          // stage `it` resident
        __syncthreads();                   // prev compute done before overwrite
        if (it + 2 < nIter) load_stage((it + 2) % NSTG, (it + 2) * BK);
        __pipeline_commit();

        const __half* sA = (const __half*)(dsm + cur * STG_BYTES);
        const __half* sB = (const __half*)(dsm + cur * STG_BYTES + A_BYTES);
        #pragma unroll
        for (int k2 = 0; k2 < BK; k2 += 16) {
            wmma::fragment<wmma::matrix_a, 16, 16, 16, __half, wmma::row_major> af[4];
            wmma::fragment<wmma::matrix_b, 16, 16, 16, __half, wmma::row_major> bf[2];
            #pragma unroll
            for (int i = 0; i < 4; i++)
                wmma::load_matrix_sync(af[i], sA + (wr * 64 + i * 16) * LDA + k2, LDA);
            #pragma unroll
            for (int j = 0; j < 2; j++)
                wmma::load_matrix_sync(bf[j], sB + k2 * LDB + wc * 32 + j * 16, LDB);
            #pragma unroll
            for (int i = 0; i < 4; i++)
                #pragma unroll
                for (int j = 0; j < 2; j++)
                    wmma::mma_sync(acc[i][j], af[i], bf[j], acc[i][j]);
        }
    }
    __syncthreads();

    // epilogue: per-warp smem staging, ONE 16B store (8 halves) per thread/frag
    float* buf = (float*)dsm + warp * 272;
    #pragma unroll
    for (int i = 0; i < 4; i++) {
        #pragma unroll
        for (int j = 0; j < 2; j++) {
            wmma::store_matrix_sync(buf, acc[i][j], 16, wmma::mem_row_major);
            __syncwarp();
            const int gr = m0 + wr * 64 + i * 16;
            const int gc = n0 + wc * 32 + j * 16;
            const int r  = lane >> 1, ch = (lane & 1) * 8;
            float vv[8];
            #pragma unroll
            for (int e = 0; e < 8; e++) {
                float v = buf[r * 16 + ch + e] + bias[gc + ch + e];
                if (EPI == 1) v = v * normcdff(v);     // exact GELU
                vv[e] = v;
            }
            __half2 hs[4];
            #pragma unroll
            for (int p = 0; p < 4; p++)
                hs[p] = __floats2half2_rn(vv[2 * p], vv[2 * p + 1]);
            *reinterpret_cast<int4*>(&Oh[(size_t)(gr + r) * N + gc + ch]) =
                *reinterpret_cast<int4*>(hs);
            __syncwarp();
        }
    }
}

// ---------------- per-token head-attention + residual + LN1 --------------------
// Q/K/V fp16 in smem as half2 (halved LDS traffic); X fp32; X1 out fp16 only.
__global__ void __launch_bounds__(256)
attn_ln1_kernel(const __half* __restrict__ Q, const __half* __restrict__ Kk,
                const __half* __restrict__ V, const float* __restrict__ X,
                const float* __restrict__ g1, const float* __restrict__ be1,
                __half* __restrict__ Oh)
{
    __shared__ uint32_t sq2[16 * 65], sk2[16 * 65], sv2[16 * 65];  // 64 half2 + pad
    __shared__ float satt[16][16];
    __shared__ float red[16];
    const int t = blockIdx.x, tid = threadIdx.x;
    const size_t base4 = (size_t)t * (DDIM / 4);
    const size_t base8 = (size_t)t * (DDIM / 8);

    // load: one int4 (8 halves = 4 half2) per thread per tensor, raw copy
    {
        int e = tid * 8, h = e >> 7, d2 = (e & 127) >> 1;
        int o = h * 65 + d2;
        int4 qa = ((const int4*)Q)[base8 + tid];
        int4 ka = ((const int4*)Kk)[base8 + tid];
        int4 va = ((const int4*)V)[base8 + tid];
        const uint32_t* qu = (const uint32_t*)&qa;
        const uint32_t* ku = (const uint32_t*)&ka;
        const uint32_t* vu = (const uint32_t*)&va;
        #pragma unroll
        for (int p = 0; p < 4; p++) {
            sq2[o + p] = qu[p];
            sk2[o + p] = ku[p];
            sv2[o + p] = vu[p];
        }
    }
    __syncthreads();

    // scores: one (h,tt) pair per thread; q broadcast within 16-thread group
    {
        int h = tid >> 4, tt = tid & 15;
        const uint32_t* qp = sq2 + h * 65;
        const uint32_t* kp = sk2 + tt * 65;
        float s = 0.f;
        #pragma unroll
        for (int d2 = 0; d2 < 64; d2++) {
            float2 qf = __half22float2(*(const __half2*)&qp[d2]);
            float2 kf = __half22float2(*(const __half2*)&kp[d2]);
            s += qf.x * kf.x + qf.y * kf.y;
        }
        satt[h][tt] = s * 0.08838834764831845f;     // 1/sqrt(128)
    }
    __syncthreads();

    if (tid < 16) {
        float mx = -1e30f;
        #pragma unroll
        for (int j = 0; j < 16; j++) mx = fmaxf(mx, satt[tid][j]);
        float sum = 0.f;
        #pragma unroll
        for (int j = 0; j < 16; j++) { float e = expf(satt[tid][j] - mx); satt[tid][j] = e; sum += e; }
        float inv = 1.f / sum;
        #pragma unroll
        for (int j = 0; j < 16; j++) satt[tid][j] *= inv;
    }
    __syncthreads();

    // y (8 contiguous elems per thread, all same head) + residual
    const int e0 = tid * 8, hh = e0 >> 7, d2b = (e0 & 127) >> 1;
    float y[8] = {0.f, 0.f, 0.f, 0.f, 0.f, 0.f, 0.f, 0.f};
    #pragma unroll
    for (int tt = 0; tt < 16; tt++) {
        float p = satt[hh][tt];
        const uint32_t* vp = sv2 + tt * 65 + d2b;
        #pragma unroll
        for (int j = 0; j < 4; j++) {
            float2 vf = __half22float2(*(const __half2*)&vp[j]);
            y[2 * j]     += p * vf.x;
            y[2 * j + 1] += p * vf.y;
        }
    }
    float xp[8];
    float ls = 0.f, lq = 0.f;
    #pragma unroll
    for (int it = 0; it < 2; it++) {
        int i4 = tid * 2 + it;
        float4 xv = ((const float4*)X)[base4 + i4];
        float v0 = xv.x + y[it*4+0], v1 = xv.y + y[it*4+1];
        float v2 = xv.z + y[it*4+2], v3 = xv.w + y[it*4+3];
        xp[it*4+0] = v0; xp[it*4+1] = v1; xp[it*4+2] = v2; xp[it*4+3] = v3;
        ls += v0 + v1 + v2 + v3;
        lq += v0*v0 + v1*v1 + v2*v2 + v3*v3;
    }
    #pragma unroll
    for (int off = 16; off; off >>= 1) {
        ls += __shfl_xor_sync(0xffffffffu, ls, off);
        lq += __shfl_xor_sync(0xffffffffu, lq, off);
    }
    if ((tid & 31) == 0) { red[tid >> 5] = ls; red[8 + (tid >> 5)] = lq; }
    __syncthreads();
    float S = 0.f, Qs = 0.f;
    #pragma unroll
    for (int w = 0; w < 8; w++) { S += red[w]; Qs += red[8 + w]; }
    float mean = S * (1.0f / DDIM);
    float var  = Qs * (1.0f / DDIM) - mean * mean;
    float inv  = rsqrtf(var + 1e-5f);

    // normalize + write fp16 (one int4 of 8 halves)
    __half2 hs[4];
    #pragma unroll
    for (int it = 0; it < 2; it++) {
        int i4 = tid * 2 + it;
        float4 g = ((const float4*)g1)[i4];
        float4 be = ((const float4*)be1)[i4];
        float v0 = (xp[it*4+0] - mean) * inv * g.x + be.x;
        float v1 = (xp[it*4+1] - mean) * inv * g.y + be.y;
        float v2 = (xp[it*4+2] - mean) * inv * g.z + be.z;
        float v3 = (xp[it*4+3] - mean) * inv * g.w + be.w;
        hs[it*2+0] = __floats2half2_rn(v0, v1);
        hs[it*2+1] = __floats2half2_rn(v2, v3);
    }
    *reinterpret_cast<int4*>(&Oh[(size_t)t * DDIM + tid * 8]) =
        *reinterpret_cast<int4*>(hs);
}

// ---------------- out = LN(A_half + B_half) * g + beta -------------------------
__global__ void __launch_bounds__(256)
add_ln_kernel(const __half* __restrict__ A, const __half* __restrict__ Bv,
              const float* __restrict__ g, const float* __restrict__ be,
              float* __restrict__ out)
{
    __shared__ float red[16];
    const int t = blockIdx.x, tid = threadIdx.x;
    const size_t base4 = (size_t)t * (DDIM / 4);
    const size_t base8 = (size_t)t * (DDIM / 8);

    int4 aa = ((const int4*)A)[base8 + tid];
    int4 ba = ((const int4*)Bv)[base8 + tid];
    const __half2* ah = (const __half2*)&aa;
    const __half2* bh = (const __half2*)&ba;
    float xp[8];
    float ls = 0.f, lq = 0.f;
    #pragma unroll
    for (int p = 0; p < 4; p++) {
        float2 af = __half22float2(ah[p]);
        float2 bf = __half22float2(bh[p]);
        float v0 = af.x + bf.x, v1 = af.y + bf.y;
        xp[2*p] = v0; xp[2*p+1] = v1;
        ls += v0 + v1;
        lq += v0*v0 + v1*v1;
    }
    #pragma unroll
    for (int off = 16; off; off >>= 1) {
        ls += __shfl_xor_sync(0xffffffffu, ls, off);
        lq += __shfl_xor_sync(0xffffffffu, lq, off);
    }
    if ((tid & 31) == 0) { red[tid >> 5] = ls; red[8 + (tid >> 5)] = lq; }
    __syncthreads();
    float S = 0.f, Qs = 0.f;
    #pragma unroll
    for (int w = 0; w < 8; w++) { S += red[w]; Qs += red[8 + w]; }
    float mean = S * (1.0f / DDIM);
    float var  = Qs * (1.0f / DDIM) - mean * mean;
    float inv  = rsqrtf(var + 1e-5f);
    #pragma unroll
    for (int it = 0; it < 2; it++) {
        int i4 = tid * 2 + it;
        float4 gg = ((const float4*)g)[i4];
        float4 be4 = ((const float4*)be)[i4];
        float4 v;
        v.x = (xp[it*4+0] - mean) * inv * gg.x + be4.x;
        v.y = (xp[it*4+1] - mean) * inv * gg.y + be4.y;
        v.z = (xp[it*4+2] - mean) * inv * gg.z + be4.z;
        v.w = (xp[it*4+3] - mean) * inv * gg.w + be4.w;
        ((float4*)out)[base4 + i4] = v;
    }
}

// ---------------- host orchestration -------------------------------------------
extern "C" void kernel_launch(void* const* d_in, const int* in_sizes, int n_in,
                              void* d_out, int out_size)
{
    const float* X     = (const float*)d_in[0];
    const float* Wq    = (const float*)d_in[1];
    const float* bq    = (const float*)d_in[2];
    const float* Wk    = (const float*)d_in[3];
    const float* bk    = (const float*)d_in[4];
    const float* Wv    = (const float*)d_in[5];
    const float* bv    = (const float*)d_in[6];
    const float* g1    = (const float*)d_in[7];
    const float* beta1 = (const float*)d_in[8];
    const float* W1    = (const float*)d_in[9];
    const float* b1    = (const float*)d_in[10];
    const float* W2    = (const float*)d_in[11];
    const float* b2    = (const float*)d_in[12];
    const float* g2    = (const float*)d_in[13];
    const float* beta2 = (const float*)d_in[14];
    float* out = (float*)d_out;

    __half *Ah, *Hh, *Wf, *Qh, *Kh, *Vh;
    cudaGetSymbolAddress((void**)&Ah, g_Ah);
    cudaGetSymbolAddress((void**)&Hh, g_Hh);
    cudaGetSymbolAddress((void**)&Wf, g_Wf);
    cudaGetSymbolAddress((void**)&Qh, g_Qh);
    cudaGetSymbolAddress((void**)&Kh, g_Kh);
    cudaGetSymbolAddress((void**)&Vh, g_Vh);

    cudaFuncSetAttribute(gemm_fp16<0>, cudaFuncAttributeMaxDynamicSharedMemorySize, GEMM_SMEM);
    cudaFuncSetAttribute(gemm_fp16<1>, cudaFuncAttributeMaxDynamicSharedMemorySize, GEMM_SMEM);

    // launch 0: X convert     launch 1: weights convert
    split_x_kernel<<<MROWS * DDIM / 4 / 256, 256>>>(X, Ah);
    {
        dim3 gw(DDIM * DDIM / 4 / 256, 5);
        split_w_kernel<<<gw, 256>>>(Wq, Wk, Wv, W1, W2, Wf);
    }

    dim3 gg(DDIM / BN, MROWS / BM);   // (16, 128)
    // launches 2..4: Q, K, V projections
    gemm_fp16<0><<<gg, 256, GEMM_SMEM>>>(Ah, Wf + 0 * WSZ, bq, Qh);
    gemm_fp16<0><<<gg, 256, GEMM_SMEM>>>(Ah, Wf + 1 * WSZ, bk, Kh);
    gemm_fp16<0><<<gg, 256, GEMM_SMEM>>>(Ah, Wf + 2 * WSZ, bv, Vh);
    // launch 5: attn + LN1 -> fp16 X1 in Ah   <-- ncu -s 5 -c 1 captures THIS
    attn_ln1_kernel<<<MROWS, 256>>>(Qh, Kh, Vh, X, g1, beta1, Ah);
    // launch 6: FFN1 (+GELU)
    gemm_fp16<1><<<gg, 256, GEMM_SMEM>>>(Ah, Wf + 3 * WSZ, b1, Hh);
    // launch 7: FFN2 (y2 reuses Qh)
    gemm_fp16<0><<<gg, 256, GEMM_SMEM>>>(Hh, Wf + 4 * WSZ, b2, Qh);
    // launch 8: final residual + LN2
    add_ln_kernel<<<MROWS, 256>>>(Ah, Qh, g2, beta2, out);
}